// round 5
// baseline (speedup 1.0000x reference)
#include <cuda_runtime.h>

#define NPTS   100000
#define BATCH  4096
#define KSEL   10
#define TPB    128
#define RPB    4       // rays per block
#define SUBS   32      // lanes per ray
#define GRID   (BATCH / RPB)   // 1024 blocks
#define UNR    4
#define NCHUNK (NPTS / (SUBS * UNR))   // 781 exact, tail = 32 points

__device__ float4 g_packed[NPTS];   // (-2x, -2y, -2z, |x|^2)

__global__ __launch_bounds__(256)
void pack_kernel(const float* __restrict__ xyz)
{
    int i = blockIdx.x * 256 + threadIdx.x;
    if (i < NPTS) {
        float x = xyz[i * 3 + 0];
        float y = xyz[i * 3 + 1];
        float z = xyz[i * 3 + 2];
        float q = fmaf(x, x, fmaf(y, y, z * z));
        g_packed[i] = make_float4(-2.0f * x, -2.0f * y, -2.0f * z, q);
    }
}

__global__ __launch_bounds__(TPB, 8)
void gs_topk_kernel(const float* __restrict__ rays_o,
                    const float* __restrict__ rays_d,
                    const float* __restrict__ fdc,
                    const float* __restrict__ opac,
                    float* __restrict__ out)
{
    __shared__ float md2 [RPB * SUBS * KSEL];
    __shared__ int   midx[RPB * SUBS * KSEL];
    __shared__ float sT[RPB];
    volatile float* sTv = sT;

    const int t       = threadIdx.x;
    const int rl      = t & (RPB - 1);
    const int sub     = t >> 2;                 // 0..31
    const int rayBase = blockIdx.x * RPB;

    float cx, cy, cz, C;
    {
        int r = rayBase + rl;
        cx = fmaf(3.0f, rays_d[r * 3 + 0], rays_o[r * 3 + 0]);
        cy = fmaf(3.0f, rays_d[r * 3 + 1], rays_o[r * 3 + 1]);
        cz = fmaf(3.0f, rays_d[r * 3 + 2], rays_o[r * 3 + 2]);
        C  = cx * cx + cy * cy + cz * cz;
    }
    if (t < RPB) sT[t] = 3.0e38f;
    __syncthreads();

    float best[KSEL];
    int   bidx[KSEL];
#pragma unroll
    for (int j = 0; j < KSEL; j++) { best[j] = 3.0e38f; bidx[j] = 0; }
    float tloc = 3.0e38f;

    const float4* p = g_packed + sub;
    int pbase = sub;

#pragma unroll 1
    for (int c = 0; c < NCHUNK; c++) {
        float Tl = fminf(sTv[rl], tloc);
        float s0, s1, s2, s3;
        {
            float4 q0 = p[0 * SUBS];
            float4 q1 = p[1 * SUBS];
            float4 q2 = p[2 * SUBS];
            float4 q3 = p[3 * SUBS];
            s0 = fmaf(cx, q0.x, fmaf(cy, q0.y, fmaf(cz, q0.z, q0.w)));
            s1 = fmaf(cx, q1.x, fmaf(cy, q1.y, fmaf(cz, q1.z, q1.w)));
            s2 = fmaf(cx, q2.x, fmaf(cy, q2.y, fmaf(cz, q2.z, q2.w)));
            s3 = fmaf(cx, q3.x, fmaf(cy, q3.y, fmaf(cz, q3.z, q3.w)));
        }
        float m = fminf(fminf(s0, s1), fminf(s2, s3));
        if (m < Tl) {
            float sv[UNR] = { s0, s1, s2, s3 };
#pragma unroll
            for (int u = 0; u < UNR; u++) {
                if (sv[u] < tloc) {
                    float v  = sv[u];
                    int   ii = pbase + u * SUBS;
#pragma unroll
                    for (int j = 0; j < KSEL; j++) {
                        if (v < best[j]) {
                            float tv = best[j]; int ti = bidx[j];
                            best[j] = v; bidx[j] = ii;
                            v = tv; ii = ti;
                        }
                    }
                    tloc = best[KSEL - 1];
                }
            }
            if (tloc < sTv[rl]) sTv[rl] = tloc;   // benign race: any stored value is a valid bound
        }
        p     += UNR * SUBS;
        pbase += UNR * SUBS;
    }
    // Tail: exactly one point per lane (99968..99999)
    {
        int k = NCHUNK * UNR * SUBS + sub;
        float4 q = g_packed[k];
        float  s = fmaf(cx, q.x, fmaf(cy, q.y, fmaf(cz, q.z, q.w)));
        if (s < fminf(sTv[rl], tloc)) {
            float v = s; int ii = k;
#pragma unroll
            for (int j = 0; j < KSEL; j++) {
                if (v < best[j]) {
                    float tv = best[j]; int ti = bidx[j];
                    best[j] = v; bidx[j] = ii;
                    v = tv; ii = ti;
                }
            }
        }
    }

    const int lbase = (rl * SUBS + sub) * KSEL;
#pragma unroll
    for (int j = 0; j < KSEL; j++) {
        md2[lbase + j]  = best[j] + C;            // back to d^2 domain
        midx[lbase + j] = bidx[j];
    }

    // Parallel pairwise merge: 32 sorted lists -> 1 per ray
    for (int stride = SUBS / 2; stride >= 1; stride >>= 1) {
        __syncthreads();
        if (sub < stride) {
            int a = (rl * SUBS + sub) * KSEL;
            int b = (rl * SUBS + sub + stride) * KSEL;
            float ov[KSEL]; int oi[KSEL];
            int ia = 0, ib = 0;
#pragma unroll
            for (int k = 0; k < KSEL; k++) {
                float va = md2[a + ia], vb = md2[b + ib];
                if (va <= vb) { ov[k] = va; oi[k] = midx[a + ia]; ia++; }
                else          { ov[k] = vb; oi[k] = midx[b + ib]; ib++; }
            }
#pragma unroll
            for (int k = 0; k < KSEL; k++) { md2[a + k] = ov[k]; midx[a + k] = oi[k]; }
        }
    }
    __syncthreads();

    // Epilogue: one thread per ray
    if (t < RPB) {
        int a = (t * SUBS) * KSEL;
        float wsum = 0.f, r0 = 0.f, g0 = 0.f, b0 = 0.f;
#pragma unroll
        for (int k = 0; k < KSEL; k++) {
            float d2 = md2[a + k];
            int   ii = midx[a + k];
            float d  = sqrtf(fmaxf(d2, 0.0f));
            float op = 1.0f / (1.0f + expf(-opac[ii]));
            float w  = expf(-0.1f * d) * op;
            wsum += w;
            float c0 = 1.0f / (1.0f + expf(-fdc[ii * 3 + 0]));
            float c1 = 1.0f / (1.0f + expf(-fdc[ii * 3 + 1]));
            float c2 = 1.0f / (1.0f + expf(-fdc[ii * 3 + 2]));
            r0 = fmaf(w, c0, r0);
            g0 = fmaf(w, c1, g0);
            b0 = fmaf(w, c2, b0);
        }
        float inv = 1.0f / (wsum + 1e-8f);
        int ray = rayBase + t;
        out[ray * 3 + 0] = r0 * inv;
        out[ray * 3 + 1] = g0 * inv;
        out[ray * 3 + 2] = b0 * inv;
    }
}

extern "C" void kernel_launch(void* const* d_in, const int* in_sizes, int n_in,
                              void* d_out, int out_size)
{
    const float* rays_o = (const float*)d_in[0];
    const float* rays_d = (const float*)d_in[1];
    const float* xyz    = (const float*)d_in[2];
    const float* fdc    = (const float*)d_in[3];
    const float* opac   = (const float*)d_in[4];
    float* out = (float*)d_out;

    pack_kernel<<<(NPTS + 255) / 256, 256>>>(xyz);
    gs_topk_kernel<<<GRID, TPB>>>(rays_o, rays_d, fdc, opac, out);
}